// round 1
// baseline (speedup 1.0000x reference)
#include <cuda_runtime.h>

// Problem shape (fixed by the reference):
//   z: (16, 3, 256, 256) f32 ; out: (16, 3, 256, 256) f32
#define HID   64
#define ZCH   3
#define TD    512
#define NB    16
#define HWP   (256 * 256)          // pixels per (b, ch) plane
#define HW4   (HWP / 4)            // float4 groups per plane = 16384

// ---------------------------------------------------------------------------
// Per-run constants (written by prep kernel, read by main kernel).
// Whole fusion collapses to: out3 = (1+sigmoid(k)) * (P*z3 + r) + ob
// with k built from dist = z'Mz + d.z + e and k_lin = q.z + s.
// ---------------------------------------------------------------------------
struct GConsts {
    float M[9];                 // A^T A (3x3, symmetric)
    float P[9];                 // W A   (3x3)
    float r[3];                 // W zb
    float ob[3];                // out bias
    float gamma, alpha, cc;     // exp(log_gamma), alpha, c
    float w0n, w1n, w2n;        // w[i] / (sum(w)+1e-8)
    float bd[NB][3];            // per-batch 2 A^T u
    float be[NB];               // per-batch |u|^2
    float bq[NB][3];            // per-batch A^T t
    float bs[NB];               // per-batch t . zb
};
__device__ GConsts g_c;

// ---------------------------------------------------------------------------
// Prep: one block per batch, 256 threads. Computes t(b) = TW @ tv(b) + tpb
// (4 lanes per output channel, 128 MACs each, shfl-reduced), then the small
// per-batch and global reductions over HID=64.
// ---------------------------------------------------------------------------
__global__ void __launch_bounds__(256) prep_kernel(
    const float* __restrict__ tv,   // (NB, TD)
    const float* __restrict__ A,    // (HID, 3) z_proj_w
    const float* __restrict__ zpb,  // (HID,)   z_proj_b
    const float* __restrict__ tw,   // (HID, TD)
    const float* __restrict__ tpb,  // (HID,)
    const float* __restrict__ W,    // (3, HID) out_w
    const float* __restrict__ ob,   // (3,)
    const float* __restrict__ lg,   // log_gamma
    const float* __restrict__ al,   // alpha
    const float* __restrict__ cp,   // c
    const float* __restrict__ wv)   // (3,)
{
    __shared__ float t_sh[HID];
    __shared__ float u_sh[HID];
    const int b   = blockIdx.x;
    const int tid = threadIdx.x;

    // --- t(b) ---
    {
        const int o    = tid >> 2;
        const int part = tid & 3;
        const float* twr = tw + o * TD + part * 128;
        const float* tvr = tv + b * TD + part * 128;
        float s = 0.f;
        #pragma unroll 8
        for (int j = 0; j < 128; j++) s = fmaf(twr[j], tvr[j], s);
        s += __shfl_xor_sync(0xffffffffu, s, 1);
        s += __shfl_xor_sync(0xffffffffu, s, 2);
        if (part == 0) {
            float tval = s + tpb[o];
            t_sh[o] = tval;
            u_sh[o] = zpb[o] - tval;   // u = zb - t
        }
    }
    __syncthreads();

    // --- per-batch reductions over HID (disjoint thread ranges) ---
    if (tid < 3) {
        float d = 0.f, q = 0.f;
        for (int o = 0; o < HID; o++) {
            float a = A[o * 3 + tid];
            d = fmaf(a, u_sh[o], d);
            q = fmaf(a, t_sh[o], q);
        }
        g_c.bd[b][tid] = 2.f * d;
        g_c.bq[b][tid] = q;
    } else if (tid == 3) {
        float e = 0.f;
        for (int o = 0; o < HID; o++) e = fmaf(u_sh[o], u_sh[o], e);
        g_c.be[b] = e;
    } else if (tid == 4) {
        float s = 0.f;
        for (int o = 0; o < HID; o++) s = fmaf(t_sh[o], zpb[o], s);
        g_c.bs[b] = s;
    }

    // --- batch-independent constants: block 0 only ---
    if (b == 0) {
        if (tid >= 8 && tid < 17) {
            int k = tid - 8, i = k / 3, j = k % 3;
            float m = 0.f;
            for (int o = 0; o < HID; o++) m = fmaf(A[o * 3 + i], A[o * 3 + j], m);
            g_c.M[k] = m;
        } else if (tid >= 17 && tid < 26) {
            int k = tid - 17, i = k / 3, j = k % 3;
            float p = 0.f;
            for (int o = 0; o < HID; o++) p = fmaf(W[i * HID + o], A[o * 3 + j], p);
            g_c.P[k] = p;
        } else if (tid >= 26 && tid < 29) {
            int i = tid - 26;
            float rr = 0.f;
            for (int o = 0; o < HID; o++) rr = fmaf(W[i * HID + o], zpb[o], rr);
            g_c.r[i] = rr;
        } else if (tid == 29) {
            g_c.gamma = expf(lg[0]);
            g_c.alpha = al[0];
            g_c.cc    = cp[0];
            float inv = 1.f / (wv[0] + wv[1] + wv[2] + 1e-8f);
            g_c.w0n = wv[0] * inv;
            g_c.w1n = wv[1] * inv;
            g_c.w2n = wv[2] * inv;
        } else if (tid >= 30 && tid < 33) {
            g_c.ob[tid - 30] = ob[tid - 30];
        }
    }
}

// ---------------------------------------------------------------------------
// Main: pure streaming. One thread = 4 pixels (float4 per channel plane).
// grid = B * HW4 / 256 blocks; batch index is uniform per block.
// ---------------------------------------------------------------------------
__global__ void __launch_bounds__(256) fused_main_kernel(
    const float* __restrict__ z, float* __restrict__ out)
{
    const unsigned g  = blockIdx.x * 256u + threadIdx.x;
    const int b  = (int)(g >> 14);        // / HW4
    const int p4 = (int)(g & (HW4 - 1));

    const float4* zb4 = (const float4*)(z   + (size_t)b * ZCH * HWP);
    float4*       ob4 = (float4*)      (out + (size_t)b * ZCH * HWP);

    const float4 v0 = zb4[p4];
    const float4 v1 = zb4[p4 + HW4];
    const float4 v2 = zb4[p4 + 2 * HW4];

    // Broadcast constant loads (L2/L1 hits, uniform across block)
    const float M00 = g_c.M[0], M11 = g_c.M[4], M22 = g_c.M[8];
    const float M01 = 2.f * g_c.M[1], M02 = 2.f * g_c.M[2], M12 = 2.f * g_c.M[5];
    const float P00 = g_c.P[0], P01 = g_c.P[1], P02 = g_c.P[2];
    const float P10 = g_c.P[3], P11 = g_c.P[4], P12 = g_c.P[5];
    const float P20 = g_c.P[6], P21 = g_c.P[7], P22 = g_c.P[8];
    const float r0 = g_c.r[0], r1 = g_c.r[1], r2 = g_c.r[2];
    const float ob0 = g_c.ob[0], ob1 = g_c.ob[1], ob2 = g_c.ob[2];
    const float ngam = -g_c.gamma, alpha = g_c.alpha, cc = g_c.cc;
    const float w0n = g_c.w0n, w1n = g_c.w1n, w2n = g_c.w2n;
    const float d0 = g_c.bd[b][0], d1 = g_c.bd[b][1], d2 = g_c.bd[b][2];
    const float e  = g_c.be[b];
    const float q0 = g_c.bq[b][0], q1 = g_c.bq[b][1], q2 = g_c.bq[b][2];
    const float s  = g_c.bs[b];

    const float a0[4] = { v0.x, v0.y, v0.z, v0.w };
    const float a1[4] = { v1.x, v1.y, v1.z, v1.w };
    const float a2[4] = { v2.x, v2.y, v2.z, v2.w };
    float o0[4], o1[4], o2[4];

    #pragma unroll
    for (int i = 0; i < 4; i++) {
        const float x = a0[i], y = a1[i], zz = a2[i];

        // dist = z'Mz + d.z + e
        float dist = e;
        dist = fmaf(M00 * x + M01 * y + M02 * zz + d0, x, dist);
        dist = fmaf(M11 * y + M12 * zz + d1,           y, dist);
        dist = fmaf(M22 * zz + d2,                     zz, dist);

        // k_lin = q.z + s
        float klin = fmaf(q0, x, fmaf(q1, y, fmaf(q2, zz, s)));

        float krbf = __expf(ngam * dist);            // underflows to 0 when dist large
        float t1   = fmaf(alpha, klin, cc);
        float kpoly = t1 * t1;
        float k = fmaf(w0n, krbf, fmaf(w1n, klin, w2n * kpoly));

        float scale = 1.f + 1.f / (1.f + __expf(-k));   // 1 + sigmoid(k)

        o0[i] = fmaf(scale, fmaf(P00, x, fmaf(P01, y, fmaf(P02, zz, r0))), ob0);
        o1[i] = fmaf(scale, fmaf(P10, x, fmaf(P11, y, fmaf(P12, zz, r1))), ob1);
        o2[i] = fmaf(scale, fmaf(P20, x, fmaf(P21, y, fmaf(P22, zz, r2))), ob2);
    }

    ob4[p4]           = make_float4(o0[0], o0[1], o0[2], o0[3]);
    ob4[p4 + HW4]     = make_float4(o1[0], o1[1], o1[2], o1[3]);
    ob4[p4 + 2 * HW4] = make_float4(o2[0], o2[1], o2[2], o2[3]);
}

// ---------------------------------------------------------------------------
extern "C" void kernel_launch(void* const* d_in, const int* in_sizes, int n_in,
                              void* d_out, int out_size)
{
    const float* z    = (const float*)d_in[0];
    const float* tv   = (const float*)d_in[1];
    const float* zpw  = (const float*)d_in[2];
    const float* zpb  = (const float*)d_in[3];
    const float* tw   = (const float*)d_in[4];
    const float* tpb  = (const float*)d_in[5];
    const float* ow   = (const float*)d_in[6];
    const float* ob   = (const float*)d_in[7];
    const float* lg   = (const float*)d_in[8];
    const float* al   = (const float*)d_in[9];
    const float* cp   = (const float*)d_in[10];
    const float* wv   = (const float*)d_in[11];
    float* out = (float*)d_out;

    const int B = in_sizes[0] / (ZCH * HWP);      // 16

    prep_kernel<<<B, 256>>>(tv, zpw, zpb, tw, tpb, ow, ob, lg, al, cp, wv);

    const int groups = B * HW4;                   // 262144
    fused_main_kernel<<<groups / 256, 256>>>(z, out);
}